// round 15
// baseline (speedup 1.0000x reference)
#include <cuda_runtime.h>
#include <cuda_fp16.h>
#include <cstdint>
#include <math.h>

#define N_RES   1024
#define NB      15
#define E_AB_LO 131072
#define E_TOT   133120
#define EPSF    1e-6f
#define TWO_PI  6.283185307179586f

#define EPB     128
#define EDGE_BLOCKS (E_TOT / EPB)     // 1040

// smem layout (bytes) — R9 skeleton
#define SO_B    0                     // 4 x 16896 = 67584
#define SO_A    67584                 // 4 x 10240 = 40960 -> 108544
#define SO_HID  67584                 // overlay A-ring (+pad): 128 x 528 = 67584 -> 135168
#define SO_META 135168                // 1024 (src/dst)
#define SO_B1b  136192                // 1024
#define SO_B2b  137216                // 512
#define SMEM_EDGE 137728

__device__ __half g_reph[N_RES * 256];
__device__ __half g_feat[E_TOT * 192];     // [geom(128) | rope(64)] per edge
__device__ float  g_R[N_RES * 9];
__device__ float  g_t[N_RES * 3];
__device__ __half g_w1h[704 * 256];
__device__ __half g_w2h[256 * 128];

// ---------- helpers ----------
__device__ __forceinline__ uint32_t smem_u32(const void* p) {
    uint32_t a;
    asm("{ .reg .u64 t; cvta.to.shared.u64 t, %1; cvt.u32.u64 %0, t; }" : "=r"(a) : "l"(p));
    return a;
}
__device__ __forceinline__ void ldmx4(uint32_t* r, uint32_t addr) {
    asm volatile("ldmatrix.sync.aligned.m8n8.x4.shared.b16 {%0,%1,%2,%3}, [%4];"
        : "=r"(r[0]), "=r"(r[1]), "=r"(r[2]), "=r"(r[3]) : "r"(addr));
}
__device__ __forceinline__ void ldmx4t(uint32_t* r, uint32_t addr) {
    asm volatile("ldmatrix.sync.aligned.m8n8.x4.trans.shared.b16 {%0,%1,%2,%3}, [%4];"
        : "=r"(r[0]), "=r"(r[1]), "=r"(r[2]), "=r"(r[3]) : "r"(addr));
}
__device__ __forceinline__ void mma16816(float* d, const uint32_t* a, uint32_t b0, uint32_t b1) {
    asm volatile("mma.sync.aligned.m16n8k16.row.col.f32.f16.f16.f32 "
        "{%0,%1,%2,%3},{%4,%5,%6,%7},{%8,%9},{%0,%1,%2,%3};"
        : "+f"(d[0]), "+f"(d[1]), "+f"(d[2]), "+f"(d[3])
        : "r"(a[0]), "r"(a[1]), "r"(a[2]), "r"(a[3]), "r"(b0), "r"(b1));
}
__device__ __forceinline__ void cpa16(uint32_t dst, const void* src) {
    asm volatile("cp.async.cg.shared.global [%0], [%1], 16;" :: "r"(dst), "l"(src));
}
#define CP_COMMIT() asm volatile("cp.async.commit_group;" ::: "memory")
#define CP_WAIT2()  asm volatile("cp.async.wait_group 2;" ::: "memory")

__device__ __forceinline__ float gelu_tanh(float x) {
    float x3 = x * x * x;
    return 0.5f * x * (1.0f + tanhf(0.7978845608028654f * (x + 0.044715f * x3)));
}

// ---------- prep kernel: residue MLP + frames + weight conversion ----------
__global__ void __launch_bounds__(256) prep_kernel(
        const float* __restrict__ emb, const float* __restrict__ ts,
        const float* __restrict__ tf,  const float* __restrict__ w1,
        const float* __restrict__ b1,  const float* __restrict__ w2,
        const float* __restrict__ b2,
        const float* __restrict__ coords,
        const float* __restrict__ w1e, const float* __restrict__ w2e) {
    const int t = threadIdx.x;
    if (blockIdx.x >= 256) {
        int g = (blockIdx.x - 256) * 256 + t;
        if (g < 704 * 256) g_w1h[g] = __float2half(w1e[g]);
        else               g_w2h[g - 704 * 256] = __float2half(w2e[g - 704 * 256]);
        if (g < N_RES) {
            const float* c = coords + g * 9;
            float ax=c[0],ay=c[1],az=c[2], bx=c[3],by=c[4],bz=c[5], cx=c[6],cy=c[7],cz=c[8];
            float v1x=cx-bx,v1y=cy-by,v1z=cz-bz, v2x=ax-bx,v2y=ay-by,v2z=az-bz;
            float n1 = sqrtf(v1x*v1x+v1y*v1y+v1z*v1z) + EPSF;
            float e1x=v1x/n1,e1y=v1y/n1,e1z=v1z/n1;
            float dp = e1x*v2x+e1y*v2y+e1z*v2z;
            float u2x=v2x-e1x*dp,u2y=v2y-e1y*dp,u2z=v2z-e1z*dp;
            float n2 = sqrtf(u2x*u2x+u2y*u2y+u2z*u2z) + EPSF;
            float e2x=u2x/n2,e2y=u2y/n2,e2z=u2z/n2;
            float e3x=e1y*e2z-e1z*e2y, e3y=e1z*e2x-e1x*e2z, e3z=e1x*e2y-e1y*e2x;
            float* R = g_R + g * 9;
            R[0]=e1x;R[1]=e2x;R[2]=e3x; R[3]=e1y;R[4]=e2y;R[5]=e3y; R[6]=e1z;R[7]=e2z;R[8]=e3z;
            g_t[g*3+0]=bx; g_t[g*3+1]=by; g_t[g*3+2]=bz;
        }
        return;
    }
    __shared__ float sx[4 * 288];
    __shared__ float sh[4 * 256];
    const int r0 = blockIdx.x * 4;
    #pragma unroll
    for (int i = 0; i < 5; ++i) {
        int idx = t + i * 256;
        if (idx < 4 * 288) {
            int row = idx / 288, col = idx - row * 288;
            float v;
            if (col < 256) v = emb[(r0 + row) * 256 + col];
            else {
                int cc = col - 256;
                float ang = TWO_PI * ts[r0 + row] * tf[cc & 15];
                v = (cc < 16) ? sinf(ang) : cosf(ang);
            }
            sx[idx] = v;
        }
    }
    __syncthreads();
    float acc[4] = {0.f, 0.f, 0.f, 0.f};
    #pragma unroll 8
    for (int k = 0; k < 288; ++k) {
        float w = __ldg(w1 + k * 256 + t);
        acc[0] += sx[k]       * w;
        acc[1] += sx[288 + k] * w;
        acc[2] += sx[576 + k] * w;
        acc[3] += sx[864 + k] * w;
    }
    float bb = b1[t];
    #pragma unroll
    for (int r = 0; r < 4; ++r) sh[r * 256 + t] = gelu_tanh(acc[r] + bb);
    __syncthreads();
    float ac2[4] = {0.f, 0.f, 0.f, 0.f};
    #pragma unroll 8
    for (int k = 0; k < 256; ++k) {
        float w = __ldg(w2 + k * 256 + t);
        ac2[0] += sh[k]       * w;
        ac2[1] += sh[256 + k] * w;
        ac2[2] += sh[512 + k] * w;
        ac2[3] += sh[768 + k] * w;
    }
    float bb2 = b2[t];
    #pragma unroll
    for (int r = 0; r < 4; ++r)
        g_reph[(r0 + r) * 256 + t] = __float2half(ac2[r] + bb2 + sx[r * 288 + t]);
}

// ---------- feat kernel: materialize [geom|rope] per edge ----------
__global__ void __launch_bounds__(256) feat_kernel(
        const float* __restrict__ w_geom, const float* __restrict__ chain_freq,
        const int* __restrict__ ri, const int* __restrict__ cid,
        const int* __restrict__ gA, const int* __restrict__ gB,
        const int* __restrict__ pid) {
    __shared__ float s_gi[128 * 28];
    __shared__ float s_dsp[128], s_scl[128];
    const int t = threadIdx.x;
    const int eg0 = blockIdx.x * 128;

    if (t < 128) {
        int e = eg0 + t, src, dst;
        if (e < E_AB_LO) { src = gA[e]; dst = gB[e]; }
        else {
            int r = e - E_AB_LO, bb = r >> 10, w = r & 1023;
            src = pid[bb * 32 + (w >> 5)];
            dst = pid[bb * 32 + (w & 31)];
        }
        float disp = (float)(ri[src] - ri[dst]) * 0.125f;
        s_dsp[t] = disp;
        s_scl[t] = ((cid[src] == cid[dst]) ? 1.0f : 0.0f) / (fabsf(disp) + 1.0f);
        float Rs[9], Rd[9];
        #pragma unroll
        for (int i = 0; i < 9; ++i) { Rs[i] = g_R[src*9+i]; Rd[i] = g_R[dst*9+i]; }
        float dx = g_t[dst*3+0]-g_t[src*3+0], dy = g_t[dst*3+1]-g_t[src*3+1], dz = g_t[dst*3+2]-g_t[src*3+2];
        float dist = sqrtf(dx*dx + dy*dy + dz*dz + EPSF);
        float* gi = s_gi + t * 28;
        #pragma unroll
        for (int i = 0; i < NB; ++i) {
            float z = (dist - (20.0f/14.0f)*(float)i) * 0.75f;
            gi[i] = expf(-0.5f * z * z);
        }
        #pragma unroll
        for (int a = 0; a < 3; ++a)
            #pragma unroll
            for (int b = 0; b < 3; ++b)
                gi[15 + a*3 + b] = Rs[a]*Rd[b] + Rs[3+a]*Rd[3+b] + Rs[6+a]*Rd[6+b];
        float inv = 1.0f / (dist + 1.0f);
        #pragma unroll
        for (int k = 0; k < 3; ++k)
            gi[24 + k] = (Rs[k]*dx + Rs[3+k]*dy + Rs[6+k]*dz) * inv;
    }
    __syncthreads();

    const int e = t >> 1, p = t & 1;
    const float* gi = s_gi + e * 28;
    __half* drow = g_feat + (size_t)(eg0 + e) * 192;

    // geom: 64 cols per thread in 4 groups of 16
    #pragma unroll
    for (int sub = 0; sub < 4; ++sub) {
        const int cb = p * 64 + sub * 16;
        float a16[16];
        #pragma unroll
        for (int j = 0; j < 16; ++j) a16[j] = 0.0f;
        #pragma unroll
        for (int k = 0; k < 27; ++k) {
            float g = gi[k];
            const float4* wg = (const float4*)(w_geom + k * 128 + cb);
            float4 w0 = wg[0], w1 = wg[1], w2 = wg[2], w3 = wg[3];
            a16[0]+=g*w0.x;  a16[1]+=g*w0.y;  a16[2]+=g*w0.z;  a16[3]+=g*w0.w;
            a16[4]+=g*w1.x;  a16[5]+=g*w1.y;  a16[6]+=g*w1.z;  a16[7]+=g*w1.w;
            a16[8]+=g*w2.x;  a16[9]+=g*w2.y;  a16[10]+=g*w2.z; a16[11]+=g*w2.w;
            a16[12]+=g*w3.x; a16[13]+=g*w3.y; a16[14]+=g*w3.z; a16[15]+=g*w3.w;
        }
        __half2 h[8];
        #pragma unroll
        for (int j = 0; j < 8; ++j) h[j] = __floats2half2_rn(a16[2*j], a16[2*j+1]);
        *(uint4*)(drow + cb)     = *(uint4*)h;
        *(uint4*)(drow + cb + 8) = *(uint4*)(h + 4);
    }
    // rope: 16 freqs per thread -> sin at 128+idx, cos at 160+idx
    float dsp = s_dsp[e], sc = s_scl[e];
    #pragma unroll
    for (int j = 0; j < 16; ++j) {
        int idx = p * 16 + j;
        float sv = 0.0f, cv = 0.0f;
        if (sc != 0.0f) {
            float ss, cc;
            __sincosf(TWO_PI * dsp * __ldg(chain_freq + idx), &ss, &cc);
            sv = ss * sc; cv = cc * sc;
        }
        drow[128 + idx] = __float2half(sv);
        drow[160 + idx] = __float2half(cv);
    }
}

// ---------- B loaders (512 threads) ----------
__device__ __forceinline__ void loadB1(int c, int t, uint32_t bbuf) {
    int r = t >> 4;
    #pragma unroll
    for (int q = 0; q < 2; ++q) {
        int s = (t & 15) * 2 + q;
        cpa16(bbuf + r * 528 + s * 16, g_w1h + (c * 32 + r) * 256 + s * 8);
    }
}
__device__ __forceinline__ void loadB2(int d, int t, uint32_t bbuf) {
    int r = t >> 4;
    int s = t & 15;
    cpa16(bbuf + r * 272 + s * 16, g_w2h + (d * 32 + r) * 128 + s * 8);
}

// uniform A staging: one cpa16 per thread
__device__ __forceinline__ void stageA(int c, int t, uint32_t abuf, int eg0,
                                       const int* s_src, const int* s_dst) {
    const int e = t >> 2, p = t & 3;
    const __half* src;
    if (c < 6)       src = g_feat + (size_t)(eg0 + e) * 192 + c * 32 + p * 8;
    else if (c < 14) src = g_reph + s_src[e] * 256 + (c - 6) * 32 + p * 8;
    else             src = g_reph + s_dst[e] * 256 + (c - 14) * 32 + p * 8;
    cpa16(abuf + e * 80 + p * 16, src);
}

__device__ __forceinline__ void stageChunk(int g, int t, uint32_t sb, int eg0,
                                           const int* s_src, const int* s_dst) {
    const int buf = g & 3;
    if (g < 22) {
        loadB1(g, t, sb + SO_B + buf * 16896);
        stageA(g, t, sb + SO_A + buf * 10240, eg0, s_src, s_dst);
    } else if (g < 30) {
        loadB2(g - 22, t, sb + SO_B + buf * 16896);
    }
}

// ---------- edge kernel: R9 skeleton, 512 threads, 16 warps (4m x 4n), M=128 ----------
__global__ void __launch_bounds__(512, 1)
edge_kernel(const float* __restrict__ b1e, const float* __restrict__ b2e,
            const int* __restrict__ gA, const int* __restrict__ gB,
            const int* __restrict__ pid, float* __restrict__ out) {
    extern __shared__ char smem[];
    const uint32_t sb = smem_u32(smem);
    const int t = threadIdx.x, wid = t >> 5, lane = t & 31;
    const int wm = wid & 3, wn = wid >> 2;
    const int m0 = wm * 32;
    const int eg0 = blockIdx.x * EPB;

    int*   s_src = (int*)(smem + SO_META);
    int*   s_dst = s_src + 128;
    float* s_b1  = (float*)(smem + SO_B1b);
    float* s_b2  = (float*)(smem + SO_B2b);
    __half* s_hid = (__half*)(smem + SO_HID);

    // hoisted per-warp LDSM offsets (bytes)
    const uint32_t lrow = lane & 15, lhi = (lane >> 4) * 8;
    const uint32_t aoff0 = (m0 + lrow) * 80 + lhi * 2;
    const uint32_t aoff1 = aoff0 + 16 * 80;
    const uint32_t boff1 = lrow * 528 + (wn * 64 + lhi) * 2;
    const uint32_t hoff0 = (m0 + lrow) * 528 + lhi * 2;
    const uint32_t hoff1 = hoff0 + 16 * 528;
    const uint32_t boff2 = lrow * 272 + (wn * 32 + lhi) * 2;

    // prologue: chunks 0..2 fully async (A from g_feat, no meta dependency)
    loadB1(0, t, sb + SO_B);
    stageA(0, t, sb + SO_A, eg0, s_src, s_dst);
    CP_COMMIT();
    loadB1(1, t, sb + SO_B + 16896);
    stageA(1, t, sb + SO_A + 10240, eg0, s_src, s_dst);
    CP_COMMIT();
    loadB1(2, t, sb + SO_B + 2 * 16896);
    stageA(2, t, sb + SO_A + 2 * 10240, eg0, s_src, s_dst);
    CP_COMMIT();

    if (t < 256) s_b1[t] = b1e[t];
    else if (t < 384) s_b2[t - 256] = b2e[t - 256];

    if (t < EPB) {
        int e = eg0 + t, src, dst;
        if (e < E_AB_LO) { src = gA[e]; dst = gB[e]; }
        else {
            int r = e - E_AB_LO, bb = r >> 10, w = r & 1023;
            src = pid[bb * 32 + (w >> 5)];
            dst = pid[bb * 32 + (w & 31)];
        }
        s_src[t] = src; s_dst[t] = dst;
    }
    __syncthreads();   // meta ready (needed from chunk 6)

    // ---- GEMM1: chunks 0..21 (stage g+3, wait2 — R9 accounting) ----
    float acc[2][8][4];
    #pragma unroll
    for (int s = 0; s < 2; ++s)
        #pragma unroll
        for (int n = 0; n < 8; ++n)
            #pragma unroll
            for (int q = 0; q < 4; ++q) acc[s][n][q] = 0.0f;

    for (int g = 0; g < 22; ++g) {
        CP_WAIT2();
        __syncthreads();
        stageChunk(g + 3, t, sb, eg0, s_src, s_dst);
        CP_COMMIT();

        const uint32_t Ab = sb + SO_A + (g & 3) * 10240;
        const uint32_t Bb = sb + SO_B + (g & 3) * 16896;

        uint32_t a[2][2][4];
        ldmx4(a[0][0], Ab + aoff0);
        ldmx4(a[0][1], Ab + aoff1);
        ldmx4(a[1][0], Ab + aoff0 + 32);
        ldmx4(a[1][1], Ab + aoff1 + 32);

        uint32_t bfr[2][4];
        ldmx4t(bfr[0], Bb + boff1);
        #pragma unroll
        for (int i = 0; i < 8; ++i) {          // i = ks*4 + np
            const int ks = i >> 2, np = i & 3, cur = i & 1;
            if (i < 7) {
                const int j = i + 1;
                ldmx4t(bfr[cur ^ 1], Bb + boff1 + (j >> 2) * 8448 + (j & 3) * 32);
            }
            mma16816(acc[0][np*2],   a[ks][0], bfr[cur][0], bfr[cur][1]);
            mma16816(acc[0][np*2+1], a[ks][0], bfr[cur][2], bfr[cur][3]);
            mma16816(acc[1][np*2],   a[ks][1], bfr[cur][0], bfr[cur][1]);
            mma16816(acc[1][np*2+1], a[ks][1], bfr[cur][2], bfr[cur][3]);
        }
    }

    // ---- epilogue 1: bias + gelu -> s_hid (overlays A ring) ----
    __syncthreads();
    {
        const int r0 = m0 + (lane >> 2);
        const int cb = wn * 64 + (lane & 3) * 2;
        #pragma unroll
        for (int sub = 0; sub < 2; ++sub) {
            int rA = r0 + sub * 16;
            #pragma unroll
            for (int nt = 0; nt < 8; ++nt) {
                int col = cb + nt * 8;
                float bb0 = s_b1[col], bb1 = s_b1[col + 1];
                float* A = acc[sub][nt];
                *(__half2*)(s_hid + rA * 264 + col) =
                    __floats2half2_rn(gelu_tanh(A[0] + bb0), gelu_tanh(A[1] + bb1));
                *(__half2*)(s_hid + (rA + 8) * 264 + col) =
                    __floats2half2_rn(gelu_tanh(A[2] + bb0), gelu_tanh(A[3] + bb1));
            }
        }
    }
    __syncthreads();

    // ---- GEMM2: chunks 22..29 ----
    float acc2[2][4][4];
    #pragma unroll
    for (int s = 0; s < 2; ++s)
        #pragma unroll
        for (int n = 0; n < 4; ++n)
            #pragma unroll
            for (int q = 0; q < 4; ++q) acc2[s][n][q] = 0.0f;

    for (int g = 22; g < 30; ++g) {
        CP_WAIT2();
        __syncthreads();
        stageChunk(g + 3, t, sb, eg0, s_src, s_dst);
        CP_COMMIT();

        const int d = g - 22;
        const uint32_t Hb = sb + SO_HID + d * 64;
        const uint32_t Bb = sb + SO_B + (g & 3) * 16896;

        uint32_t a[2][2][4];
        ldmx4(a[0][0], Hb + hoff0);
        ldmx4(a[0][1], Hb + hoff1);
        ldmx4(a[1][0], Hb + hoff0 + 32);
        ldmx4(a[1][1], Hb + hoff1 + 32);

        uint32_t bfr[2][4];
        ldmx4t(bfr[0], Bb + boff2);
        #pragma unroll
        for (int i = 0; i < 4; ++i) {          // i = ks*2 + np
            const int ks = i >> 1, np = i & 1, cur = i & 1;
            if (i < 3) {
                const int j = i + 1;
                ldmx4t(bfr[cur ^ 1], Bb + boff2 + (j >> 1) * 4352 + (j & 1) * 32);
            }
            mma16816(acc2[0][np*2],   a[ks][0], bfr[cur][0], bfr[cur][1]);
            mma16816(acc2[0][np*2+1], a[ks][0], bfr[cur][2], bfr[cur][3]);
            mma16816(acc2[1][np*2],   a[ks][1], bfr[cur][0], bfr[cur][1]);
            mma16816(acc2[1][np*2+1], a[ks][1], bfr[cur][2], bfr[cur][3]);
        }
    }

    // ---- epilogue 2: bias + store ----
    {
        const int r0 = m0 + (lane >> 2);
        const int cb = wn * 32 + (lane & 3) * 2;
        #pragma unroll
        for (int sub = 0; sub < 2; ++sub) {
            int rA = r0 + sub * 16;
            int eg = eg0 + rA;
            #pragma unroll
            for (int nt = 0; nt < 4; ++nt) {
                int col = cb + nt * 8;
                float bb0 = s_b2[col], bb1 = s_b2[col + 1];
                float* A = acc2[sub][nt];
                *(float2*)(out + eg * 128 + col)       = make_float2(A[0] + bb0, A[1] + bb1);
                *(float2*)(out + (eg + 8) * 128 + col) = make_float2(A[2] + bb0, A[3] + bb1);
            }
        }
    }
}

// ---------- launch ----------
extern "C" void kernel_launch(void* const* d_in, const int* in_sizes, int n_in,
                              void* d_out, int out_size) {
    const float* emb        = (const float*)d_in[0];
    const float* ts         = (const float*)d_in[1];
    const float* coords     = (const float*)d_in[2];
    const float* time_freq  = (const float*)d_in[3];
    const float* chain_freq = (const float*)d_in[4];
    const float* w1_res     = (const float*)d_in[5];
    const float* b1_res     = (const float*)d_in[6];
    const float* w2_res     = (const float*)d_in[7];
    const float* b2_res     = (const float*)d_in[8];
    const float* w_geom     = (const float*)d_in[9];
    const float* w1_edge    = (const float*)d_in[10];
    const float* b1_edge    = (const float*)d_in[11];
    const float* w2_edge    = (const float*)d_in[12];
    const float* b2_edge    = (const float*)d_in[13];
    const int*   ri         = (const int*)d_in[14];
    const int*   cid        = (const int*)d_in[15];
    const int*   gA         = (const int*)d_in[16];
    const int*   gB         = (const int*)d_in[17];
    const int*   pid        = (const int*)d_in[18];
    float* out = (float*)d_out;

    cudaFuncSetAttribute(edge_kernel, cudaFuncAttributeMaxDynamicSharedMemorySize, SMEM_EDGE);

    prep_kernel<<<1088, 256>>>(emb, ts, time_freq, w1_res, b1_res, w2_res, b2_res,
                               coords, w1_edge, w2_edge);
    feat_kernel<<<EDGE_BLOCKS, 256>>>(w_geom, chain_freq, ri, cid, gA, gB, pid);
    edge_kernel<<<EDGE_BLOCKS, 512, SMEM_EDGE>>>(b1_edge, b2_edge, gA, gB, pid, out);
}

// round 16
// speedup vs baseline: 1.5171x; 1.5171x over previous
#include <cuda_runtime.h>
#include <cuda_fp16.h>
#include <cstdint>
#include <math.h>

#define N_RES   1024
#define NB      15
#define E_AB_LO 131072
#define E_TOT   133120
#define EPSF    1e-6f
#define TWO_PI  6.283185307179586f

#define EPB     128
#define EDGE_BLOCKS (E_TOT / EPB)     // 1040

// smem layout: 4-deep rings (R9 layout)
#define SO_B    0                     // 4 x 16896 = 67584
#define SO_A    67584                 // 4 x 10240 = 40960 -> 108544
#define SO_GI   108544                // 14336 -> 122880
#define SO_META 122880                // 2048  -> 124928
#define SO_HID  67584                 // overlay A/GI/META
#define SO_B1   135168                // 1024
#define SO_B2   136192                // 512
#define SMEM_EDGE 136704

__device__ __half g_reph[N_RES * 256];
__device__ float  g_R[N_RES * 9];
__device__ float  g_t[N_RES * 3];
__device__ __half g_w1h[704 * 256];
__device__ __half g_w2h[256 * 128];

// ---------- helpers ----------
__device__ __forceinline__ uint32_t smem_u32(const void* p) {
    uint32_t a;
    asm("{ .reg .u64 t; cvta.to.shared.u64 t, %1; cvt.u32.u64 %0, t; }" : "=r"(a) : "l"(p));
    return a;
}
__device__ __forceinline__ void ldmx4(uint32_t* r, uint32_t addr) {
    asm volatile("ldmatrix.sync.aligned.m8n8.x4.shared.b16 {%0,%1,%2,%3}, [%4];"
        : "=r"(r[0]), "=r"(r[1]), "=r"(r[2]), "=r"(r[3]) : "r"(addr));
}
__device__ __forceinline__ void ldmx4t(uint32_t* r, uint32_t addr) {
    asm volatile("ldmatrix.sync.aligned.m8n8.x4.trans.shared.b16 {%0,%1,%2,%3}, [%4];"
        : "=r"(r[0]), "=r"(r[1]), "=r"(r[2]), "=r"(r[3]) : "r"(addr));
}
__device__ __forceinline__ void mma16816(float* d, const uint32_t* a, uint32_t b0, uint32_t b1) {
    asm volatile("mma.sync.aligned.m16n8k16.row.col.f32.f16.f16.f32 "
        "{%0,%1,%2,%3},{%4,%5,%6,%7},{%8,%9},{%0,%1,%2,%3};"
        : "+f"(d[0]), "+f"(d[1]), "+f"(d[2]), "+f"(d[3])
        : "r"(a[0]), "r"(a[1]), "r"(a[2]), "r"(a[3]), "r"(b0), "r"(b1));
}
__device__ __forceinline__ void cpa16(uint32_t dst, const void* src) {
    asm volatile("cp.async.cg.shared.global [%0], [%1], 16;" :: "r"(dst), "l"(src));
}
#define CP_COMMIT() asm volatile("cp.async.commit_group;" ::: "memory")
#define CP_WAIT2()  asm volatile("cp.async.wait_group 2;" ::: "memory")

__device__ __forceinline__ float gelu_tanh(float x) {
    float x3 = x * x * x;
    return 0.5f * x * (1.0f + tanhf(0.7978845608028654f * (x + 0.044715f * x3)));
}

// ---------- prep kernel ----------
__global__ void __launch_bounds__(256) prep_kernel(
        const float* __restrict__ emb, const float* __restrict__ ts,
        const float* __restrict__ tf,  const float* __restrict__ w1,
        const float* __restrict__ b1,  const float* __restrict__ w2,
        const float* __restrict__ b2,
        const float* __restrict__ coords,
        const float* __restrict__ w1e, const float* __restrict__ w2e) {
    const int t = threadIdx.x;
    if (blockIdx.x >= 256) {
        int g = (blockIdx.x - 256) * 256 + t;
        if (g < 704 * 256) g_w1h[g] = __float2half(w1e[g]);
        else               g_w2h[g - 704 * 256] = __float2half(w2e[g - 704 * 256]);
        if (g < N_RES) {
            const float* c = coords + g * 9;
            float ax=c[0],ay=c[1],az=c[2], bx=c[3],by=c[4],bz=c[5], cx=c[6],cy=c[7],cz=c[8];
            float v1x=cx-bx,v1y=cy-by,v1z=cz-bz, v2x=ax-bx,v2y=ay-by,v2z=az-bz;
            float n1 = sqrtf(v1x*v1x+v1y*v1y+v1z*v1z) + EPSF;
            float e1x=v1x/n1,e1y=v1y/n1,e1z=v1z/n1;
            float dp = e1x*v2x+e1y*v2y+e1z*v2z;
            float u2x=v2x-e1x*dp,u2y=v2y-e1y*dp,u2z=v2z-e1z*dp;
            float n2 = sqrtf(u2x*u2x+u2y*u2y+u2z*u2z) + EPSF;
            float e2x=u2x/n2,e2y=u2y/n2,e2z=u2z/n2;
            float e3x=e1y*e2z-e1z*e2y, e3y=e1z*e2x-e1x*e2z, e3z=e1x*e2y-e1y*e2x;
            float* R = g_R + g * 9;
            R[0]=e1x;R[1]=e2x;R[2]=e3x; R[3]=e1y;R[4]=e2y;R[5]=e3y; R[6]=e1z;R[7]=e2z;R[8]=e3z;
            g_t[g*3+0]=bx; g_t[g*3+1]=by; g_t[g*3+2]=bz;
        }
        return;
    }
    __shared__ float sx[4 * 288];
    __shared__ float sh[4 * 256];
    const int r0 = blockIdx.x * 4;
    #pragma unroll
    for (int i = 0; i < 5; ++i) {
        int idx = t + i * 256;
        if (idx < 4 * 288) {
            int row = idx / 288, col = idx - row * 288;
            float v;
            if (col < 256) v = emb[(r0 + row) * 256 + col];
            else {
                int cc = col - 256;
                float ang = TWO_PI * ts[r0 + row] * tf[cc & 15];
                v = (cc < 16) ? sinf(ang) : cosf(ang);
            }
            sx[idx] = v;
        }
    }
    __syncthreads();
    float acc[4] = {0.f, 0.f, 0.f, 0.f};
    #pragma unroll 8
    for (int k = 0; k < 288; ++k) {
        float w = __ldg(w1 + k * 256 + t);
        acc[0] += sx[k]       * w;
        acc[1] += sx[288 + k] * w;
        acc[2] += sx[576 + k] * w;
        acc[3] += sx[864 + k] * w;
    }
    float bb = b1[t];
    #pragma unroll
    for (int r = 0; r < 4; ++r) sh[r * 256 + t] = gelu_tanh(acc[r] + bb);
    __syncthreads();
    float ac2[4] = {0.f, 0.f, 0.f, 0.f};
    #pragma unroll 8
    for (int k = 0; k < 256; ++k) {
        float w = __ldg(w2 + k * 256 + t);
        ac2[0] += sh[k]       * w;
        ac2[1] += sh[256 + k] * w;
        ac2[2] += sh[512 + k] * w;
        ac2[3] += sh[768 + k] * w;
    }
    float bb2 = b2[t];
    #pragma unroll
    for (int r = 0; r < 4; ++r)
        g_reph[(r0 + r) * 256 + t] = __float2half(ac2[r] + bb2 + sx[r * 288 + t]);
}

// ---------- A chunk staging ----------
__device__ __forceinline__ void stageA(int c, int t, uint32_t abuf_u32, __half* abuf_h,
        const float* s_gi, const int* s_src, const int* s_dst,
        const float* s_dsp, const float* s_scl,
        const float* __restrict__ w_geom, const float* __restrict__ chain_freq) {
    const int e = t >> 2, p = t & 3;
    if (c >= 6) {
        int idx = (c < 14) ? s_src[e] : s_dst[e];
        int off = (c < 14) ? (c - 6) * 32 : (c - 14) * 32;
        cpa16(abuf_u32 + e * 80 + p * 16, g_reph + idx * 256 + off + p * 8);
    } else if (c >= 4) {
        float dsp = s_dsp[e], sc = s_scl[e];
        __half2 h[4];
        if (sc == 0.0f) {
            #pragma unroll
            for (int j = 0; j < 4; ++j) h[j] = __floats2half2_rn(0.0f, 0.0f);
        } else {
            #pragma unroll
            for (int j = 0; j < 4; ++j) {
                int i0 = (c - 4) * 32 + p * 8 + 2 * j, i1 = i0 + 1;
                float a0 = TWO_PI * dsp * __ldg(chain_freq + (i0 & 31));
                float a1 = TWO_PI * dsp * __ldg(chain_freq + (i1 & 31));
                float v0 = ((i0 < 32) ? __sinf(a0) : __cosf(a0)) * sc;
                float v1 = ((i1 < 32) ? __sinf(a1) : __cosf(a1)) * sc;
                h[j] = __floats2half2_rn(v0, v1);
            }
        }
        *(uint4*)(abuf_h + e * 40 + p * 8) = *(uint4*)h;
    } else {
        const float* gi = s_gi + e * 28;
        float a8[8];
        #pragma unroll
        for (int j = 0; j < 8; ++j) a8[j] = 0.0f;
        const float* wg0 = w_geom + c * 32 + p * 8;
        #pragma unroll
        for (int k = 0; k < 27; ++k) {
            float g = gi[k];
            const float4* wg = (const float4*)(wg0 + k * 128);
            float4 w0 = wg[0], w1 = wg[1];
            a8[0]+=g*w0.x; a8[1]+=g*w0.y; a8[2]+=g*w0.z; a8[3]+=g*w0.w;
            a8[4]+=g*w1.x; a8[5]+=g*w1.y; a8[6]+=g*w1.z; a8[7]+=g*w1.w;
        }
        __half2 h[4];
        #pragma unroll
        for (int j = 0; j < 4; ++j) h[j] = __floats2half2_rn(a8[2*j], a8[2*j+1]);
        *(uint4*)(abuf_h + e * 40 + p * 8) = *(uint4*)h;
    }
}

// ---------- B chunk loaders ----------
__device__ __forceinline__ void loadB1(int c, int t, uint32_t bbuf) {
    int r = t >> 4;
    #pragma unroll
    for (int q = 0; q < 2; ++q) {
        int s = (t & 15) * 2 + q;
        cpa16(bbuf + r * 528 + s * 16, g_w1h + (c * 32 + r) * 256 + s * 8);
    }
}
__device__ __forceinline__ void loadB2(int d, int t, uint32_t bbuf) {
    int r = t >> 4;
    int s = t & 15;
    cpa16(bbuf + r * 272 + s * 16, g_w2h + (d * 32 + r) * 128 + s * 8);
}

// unified staging: global chunk g in [0,30); g<22 -> B1+A chunk g; else B2 chunk g-22
__device__ __forceinline__ void stageChunk(int g, int t, uint32_t sb,
        const float* s_gi, const int* s_src, const int* s_dst,
        const float* s_dsp, const float* s_scl,
        const float* __restrict__ w_geom, const float* __restrict__ chain_freq,
        char* smem) {
    const int buf = g & 3;
    if (g < 22) {
        loadB1(g, t, sb + SO_B + buf * 16896);
        stageA(g, t, sb + SO_A + buf * 10240, (__half*)(smem + SO_A + buf * 10240),
               s_gi, s_src, s_dst, s_dsp, s_scl, w_geom, chain_freq);
    } else if (g < 30) {
        loadB2(g - 22, t, sb + SO_B + buf * 16896);
    }
}

// ---------- fused edge kernel: 512 threads, 16 warps (4m x 4n), M=128 ----------
__global__ void __launch_bounds__(512, 1)
edge_kernel(const float* __restrict__ w_geom, const float* __restrict__ chain_freq,
            const float* __restrict__ b1e, const float* __restrict__ b2e,
            const int* __restrict__ ri, const int* __restrict__ cid,
            const int* __restrict__ gA, const int* __restrict__ gB,
            const int* __restrict__ pid, float* __restrict__ out) {
    extern __shared__ char smem[];
    const uint32_t sb = smem_u32(smem);
    const int t = threadIdx.x, wid = t >> 5, lane = t & 31;
    const int wm = wid & 3, wn = wid >> 2;
    const int m0 = wm * 32;

    float* s_gi  = (float*)(smem + SO_GI);
    int*   s_src = (int*)(smem + SO_META);
    int*   s_dst = s_src + 128;
    float* s_dsp = (float*)(s_dst + 128);
    float* s_scl = s_dsp + 128;
    float* s_b1  = (float*)(smem + SO_B1);
    float* s_b2  = (float*)(smem + SO_B2);
    __half* s_hid = (__half*)(smem + SO_HID);

    // hoisted per-warp LDSM offsets (bytes)
    const uint32_t lrow = lane & 15, lhi = (lane >> 4) * 8;
    const uint32_t aoff0 = (m0 + lrow) * 80 + lhi * 2;
    const uint32_t aoff1 = aoff0 + 16 * 80;
    const uint32_t boff1 = lrow * 528 + (wn * 64 + lhi) * 2;
    const uint32_t hoff0 = (m0 + lrow) * 528 + lhi * 2;
    const uint32_t hoff1 = hoff0 + 16 * 528;
    const uint32_t boff2 = lrow * 272 + (wn * 32 + lhi) * 2;

    // group g0 = B1 chunk 0 copies
    loadB1(0, t, sb + SO_B);
    CP_COMMIT();

    if (t < 256) s_b1[t] = b1e[t];
    else if (t < 384) s_b2[t - 256] = b2e[t - 256];

    if (t < EPB) {
        int e = blockIdx.x * EPB + t, src, dst;
        if (e < E_AB_LO) { src = gA[e]; dst = gB[e]; }
        else {
            int r = e - E_AB_LO, bb = r >> 10, w = r & 1023;
            src = pid[bb * 32 + (w >> 5)];
            dst = pid[bb * 32 + (w & 31)];
        }
        s_src[t] = src; s_dst[t] = dst;
        float disp = (float)(ri[src] - ri[dst]) * 0.125f;
        s_dsp[t] = disp;
        s_scl[t] = ((cid[src] == cid[dst]) ? 1.0f : 0.0f) / (fabsf(disp) + 1.0f);
        float Rs[9], Rd[9];
        #pragma unroll
        for (int i = 0; i < 9; ++i) { Rs[i] = g_R[src*9+i]; Rd[i] = g_R[dst*9+i]; }
        float dx = g_t[dst*3+0]-g_t[src*3+0], dy = g_t[dst*3+1]-g_t[src*3+1], dz = g_t[dst*3+2]-g_t[src*3+2];
        float dist = sqrtf(dx*dx + dy*dy + dz*dz + EPSF);
        float* gi = s_gi + t * 28;
        #pragma unroll
        for (int i = 0; i < NB; ++i) {
            float z = (dist - (20.0f/14.0f)*(float)i) * 0.75f;
            gi[i] = __expf(-0.5f * z * z);
        }
        #pragma unroll
        for (int a = 0; a < 3; ++a)
            #pragma unroll
            for (int b = 0; b < 3; ++b)
                gi[15 + a*3 + b] = Rs[a]*Rd[b] + Rs[3+a]*Rd[3+b] + Rs[6+a]*Rd[6+b];
        float inv = 1.0f / (dist + 1.0f);
        #pragma unroll
        for (int k = 0; k < 3; ++k)
            gi[24 + k] = (Rs[k]*dx + Rs[3+k]*dy + Rs[6+k]*dz) * inv;
    }
    __syncthreads();   // gi/meta ready

    // prologue: A chunks 0..2 (pure STS, geom) + B1 chunks 1,2 as groups g1,g2
    stageA(0, t, sb + SO_A, (__half*)(smem + SO_A), s_gi, s_src, s_dst, s_dsp, s_scl, w_geom, chain_freq);
    stageA(1, t, sb + SO_A + 10240, (__half*)(smem + SO_A + 10240), s_gi, s_src, s_dst, s_dsp, s_scl, w_geom, chain_freq);
    stageA(2, t, sb + SO_A + 20480, (__half*)(smem + SO_A + 20480), s_gi, s_src, s_dst, s_dsp, s_scl, w_geom, chain_freq);
    loadB1(1, t, sb + SO_B + 16896);
    CP_COMMIT();
    loadB1(2, t, sb + SO_B + 2 * 16896);
    CP_COMMIT();

    // ---- GEMM1: chunks g = 0..21 ----
    float acc[2][8][4];
    #pragma unroll
    for (int s = 0; s < 2; ++s)
        #pragma unroll
        for (int n = 0; n < 8; ++n)
            #pragma unroll
            for (int q = 0; q < 4; ++q) acc[s][n][q] = 0.0f;

    for (int g = 0; g < 22; ++g) {
        CP_WAIT2();
        __syncthreads();
        stageChunk(g + 3, t, sb, s_gi, s_src, s_dst, s_dsp, s_scl, w_geom, chain_freq, smem);
        CP_COMMIT();

        const uint32_t Ab = sb + SO_A + (g & 3) * 10240;
        const uint32_t Bb = sb + SO_B + (g & 3) * 16896;

        // load all A fragments up front
        uint32_t a[2][2][4];
        ldmx4(a[0][0], Ab + aoff0);
        ldmx4(a[0][1], Ab + aoff1);
        ldmx4(a[1][0], Ab + aoff0 + 32);
        ldmx4(a[1][1], Ab + aoff1 + 32);

        // software-pipelined B: one LDSM ahead
        uint32_t bfr[2][4];
        ldmx4t(bfr[0], Bb + boff1);
        #pragma unroll
        for (int i = 0; i < 8; ++i) {          // i = ks*4 + np
            const int ks = i >> 2, np = i & 3;
            const int cur = i & 1;
            if (i < 7) {
                const int j = i + 1;
                ldmx4t(bfr[cur ^ 1], Bb + boff1 + (j >> 2) * 8448 + (j & 3) * 32);
            }
            mma16816(acc[0][np*2],   a[ks][0], bfr[cur][0], bfr[cur][1]);
            mma16816(acc[0][np*2+1], a[ks][0], bfr[cur][2], bfr[cur][3]);
            mma16816(acc[1][np*2],   a[ks][1], bfr[cur][0], bfr[cur][1]);
            mma16816(acc[1][np*2+1], a[ks][1], bfr[cur][2], bfr[cur][3]);
        }
    }

    // ---- epilogue 1: bias + gelu -> s_hid (overlay) ----
    __syncthreads();
    {
        const int r0 = m0 + (lane >> 2);
        const int cb = wn * 64 + (lane & 3) * 2;
        #pragma unroll
        for (int sub = 0; sub < 2; ++sub) {
            int rA = r0 + sub * 16;
            #pragma unroll
            for (int nt = 0; nt < 8; ++nt) {
                int col = cb + nt * 8;
                float bb0 = s_b1[col], bb1 = s_b1[col + 1];
                float* A = acc[sub][nt];
                *(__half2*)(s_hid + rA * 264 + col) =
                    __floats2half2_rn(gelu_tanh(A[0] + bb0), gelu_tanh(A[1] + bb1));
                *(__half2*)(s_hid + (rA + 8) * 264 + col) =
                    __floats2half2_rn(gelu_tanh(A[2] + bb0), gelu_tanh(A[3] + bb1));
            }
        }
    }
    __syncthreads();

    // ---- GEMM2: chunks g = 22..29 (B2 ring continues) ----
    float acc2[2][4][4];
    #pragma unroll
    for (int s = 0; s < 2; ++s)
        #pragma unroll
        for (int n = 0; n < 4; ++n)
            #pragma unroll
            for (int q = 0; q < 4; ++q) acc2[s][n][q] = 0.0f;

    for (int g = 22; g < 30; ++g) {
        CP_WAIT2();
        __syncthreads();
        stageChunk(g + 3, t, sb, s_gi, s_src, s_dst, s_dsp, s_scl, w_geom, chain_freq, smem);
        CP_COMMIT();

        const int d = g - 22;
        const uint32_t Hb = sb + SO_HID + d * 64;
        const uint32_t Bb = sb + SO_B + (g & 3) * 16896;

        uint32_t a[2][2][4];
        ldmx4(a[0][0], Hb + hoff0);
        ldmx4(a[0][1], Hb + hoff1);
        ldmx4(a[1][0], Hb + hoff0 + 32);
        ldmx4(a[1][1], Hb + hoff1 + 32);

        uint32_t bfr[2][4];
        ldmx4t(bfr[0], Bb + boff2);
        #pragma unroll
        for (int i = 0; i < 4; ++i) {          // i = ks*2 + np
            const int ks = i >> 1, np = i & 1;
            const int cur = i & 1;
            if (i < 3) {
                const int j = i + 1;
                ldmx4t(bfr[cur ^ 1], Bb + boff2 + (j >> 1) * 4352 + (j & 1) * 32);
            }
            mma16816(acc2[0][np*2],   a[ks][0], bfr[cur][0], bfr[cur][1]);
            mma16816(acc2[0][np*2+1], a[ks][0], bfr[cur][2], bfr[cur][3]);
            mma16816(acc2[1][np*2],   a[ks][1], bfr[cur][0], bfr[cur][1]);
            mma16816(acc2[1][np*2+1], a[ks][1], bfr[cur][2], bfr[cur][3]);
        }
    }

    // ---- epilogue 2: bias + store ----
    {
        const int r0 = m0 + (lane >> 2);
        const int cb = wn * 32 + (lane & 3) * 2;
        #pragma unroll
        for (int sub = 0; sub < 2; ++sub) {
            int rA = r0 + sub * 16;
            int eg0 = blockIdx.x * EPB + rA;
            #pragma unroll
            for (int nt = 0; nt < 4; ++nt) {
                int col = cb + nt * 8;
                float bb0 = s_b2[col], bb1 = s_b2[col + 1];
                float* A = acc2[sub][nt];
                *(float2*)(out + eg0 * 128 + col)       = make_float2(A[0] + bb0, A[1] + bb1);
                *(float2*)(out + (eg0 + 8) * 128 + col) = make_float2(A[2] + bb0, A[3] + bb1);
            }
        }
    }
}

// ---------- launch ----------
extern "C" void kernel_launch(void* const* d_in, const int* in_sizes, int n_in,
                              void* d_out, int out_size) {
    const float* emb        = (const float*)d_in[0];
    const float* ts         = (const float*)d_in[1];
    const float* coords     = (const float*)d_in[2];
    const float* time_freq  = (const float*)d_in[3];
    const float* chain_freq = (const float*)d_in[4];
    const float* w1_res     = (const float*)d_in[5];
    const float* b1_res     = (const float*)d_in[6];
    const float* w2_res     = (const float*)d_in[7];
    const float* b2_res     = (const float*)d_in[8];
    const float* w_geom     = (const float*)d_in[9];
    const float* w1_edge    = (const float*)d_in[10];
    const float* b1_edge    = (const float*)d_in[11];
    const float* w2_edge    = (const float*)d_in[12];
    const float* b2_edge    = (const float*)d_in[13];
    const int*   ri         = (const int*)d_in[14];
    const int*   cid        = (const int*)d_in[15];
    const int*   gA         = (const int*)d_in[16];
    const int*   gB         = (const int*)d_in[17];
    const int*   pid        = (const int*)d_in[18];
    float* out = (float*)d_out;

    cudaFuncSetAttribute(edge_kernel, cudaFuncAttributeMaxDynamicSharedMemorySize, SMEM_EDGE);

    prep_kernel<<<1088, 256>>>(emb, ts, time_freq, w1_res, b1_res, w2_res, b2_res,
                               coords, w1_edge, w2_edge);
    edge_kernel<<<EDGE_BLOCKS, 512, SMEM_EDGE>>>(
        w_geom, chain_freq, b1_edge, b2_edge, ri, cid, gA, gB, pid, out);
}